// round 1
// baseline (speedup 1.0000x reference)
#include <cuda_runtime.h>

#define BATCH 4
#define CH    256
#define NPIX  4096
#define NGRP  32
#define CPG   8

// Scratch (device globals: allocation-free per harness rules)
__device__ float g_q[BATCH * CH * NPIX];                 // 16.8 MB
__device__ float g_k[BATCH * CH * NPIX];                 // 16.8 MB
__device__ float g_S[(size_t)BATCH * NPIX * NPIX];       // 268 MB logits
__device__ float g_mx[BATCH * NPIX];
__device__ float g_rs[BATCH * NPIX];

// ---------------------------------------------------------------------------
// Warp/block reduction helpers
// ---------------------------------------------------------------------------
__device__ __forceinline__ float warpMax(float v) {
    #pragma unroll
    for (int o = 16; o > 0; o >>= 1)
        v = fmaxf(v, __shfl_xor_sync(0xffffffffu, v, o));
    return v;
}
__device__ __forceinline__ float warpSum(float v) {
    #pragma unroll
    for (int o = 16; o > 0; o >>= 1)
        v += __shfl_xor_sync(0xffffffffu, v, o);
    return v;
}

// ---------------------------------------------------------------------------
// 1) Projection: out[b,o,n] = bias[o] + sum_c W[o,c] * X[b,c,n]
//    which==0 -> g_q, which==1 -> g_k
//    Tiles: 128(o) x 128(n), BK=8, 256 threads, 8x8 per thread, double-buffered
// ---------------------------------------------------------------------------
__global__ __launch_bounds__(256, 2)
void proj_kernel(const float* __restrict__ W, const float* __restrict__ bias,
                 const float* __restrict__ X, int which)
{
    __shared__ float Ws[2][8][128];
    __shared__ float Xs[2][8][128];
    float* out = which ? g_k : g_q;

    const int n0 = blockIdx.x * 128;
    const int o0 = blockIdx.y * 128;
    const int b  = blockIdx.z;
    const int tid = threadIdx.x;
    const int tx = tid & 15, ty = tid >> 4;

    const int wo = tid >> 1;            // 0..127 (o row in tile)
    const int wc = (tid & 1) << 2;      // 0 or 4 (c)
    const int xc = tid >> 5;            // 0..7
    const int xn = (tid & 31) << 2;     // 0..124

    const float* Wp = W + (size_t)(o0 + wo) * CH + wc;
    const float* Xp = X + (size_t)b * CH * NPIX + (size_t)xc * NPIX + n0 + xn;

    float4 wr = *(const float4*)Wp;
    float4 xr = *(const float4*)Xp;
    Ws[0][wc + 0][wo] = wr.x; Ws[0][wc + 1][wo] = wr.y;
    Ws[0][wc + 2][wo] = wr.z; Ws[0][wc + 3][wo] = wr.w;
    *(float4*)&Xs[0][xc][xn] = xr;
    __syncthreads();

    float acc[8][8];
    #pragma unroll
    for (int i = 0; i < 8; ++i)
        #pragma unroll
        for (int j = 0; j < 8; ++j) acc[i][j] = 0.f;

    const int KT = CH / 8;  // 32
    for (int kt = 0; kt < KT; ++kt) {
        const int cur = kt & 1, nxt = cur ^ 1;
        if (kt + 1 < KT) {
            wr = *(const float4*)(Wp + (kt + 1) * 8);
            xr = *(const float4*)(Xp + (size_t)(kt + 1) * 8 * NPIX);
        }
        #pragma unroll
        for (int kk = 0; kk < 8; ++kk) {
            float a[8], bb[8];
            *(float4*)&a[0]  = *(float4*)&Ws[cur][kk][ty * 8];
            *(float4*)&a[4]  = *(float4*)&Ws[cur][kk][ty * 8 + 4];
            *(float4*)&bb[0] = *(float4*)&Xs[cur][kk][tx * 8];
            *(float4*)&bb[4] = *(float4*)&Xs[cur][kk][tx * 8 + 4];
            #pragma unroll
            for (int i = 0; i < 8; ++i)
                #pragma unroll
                for (int j = 0; j < 8; ++j)
                    acc[i][j] = fmaf(a[i], bb[j], acc[i][j]);
        }
        if (kt + 1 < KT) {
            Ws[nxt][wc + 0][wo] = wr.x; Ws[nxt][wc + 1][wo] = wr.y;
            Ws[nxt][wc + 2][wo] = wr.z; Ws[nxt][wc + 3][wo] = wr.w;
            *(float4*)&Xs[nxt][xc][xn] = xr;
        }
        __syncthreads();
    }

    float* op = out + (size_t)b * CH * NPIX + (size_t)(o0 + ty * 8) * NPIX + n0 + tx * 8;
    #pragma unroll
    for (int i = 0; i < 8; ++i) {
        const float bv = bias[o0 + ty * 8 + i];
        float4 v0 = make_float4(acc[i][0] + bv, acc[i][1] + bv, acc[i][2] + bv, acc[i][3] + bv);
        float4 v1 = make_float4(acc[i][4] + bv, acc[i][5] + bv, acc[i][6] + bv, acc[i][7] + bv);
        *(float4*)(op + (size_t)i * NPIX)     = v0;
        *(float4*)(op + (size_t)i * NPIX + 4) = v1;
    }
}

// ---------------------------------------------------------------------------
// 2) Logits: S[b,n,m] = sum_c q[b,c,n] * k[b,c,m]
//    Tiles: 128(n) x 128(m), BK=8 over c, double-buffered
// ---------------------------------------------------------------------------
__global__ __launch_bounds__(256, 2)
void sgemm_kernel()
{
    __shared__ float Qs[2][8][128];
    __shared__ float Ks[2][8][128];
    const int m0 = blockIdx.x * 128;
    const int n0 = blockIdx.y * 128;
    const int b  = blockIdx.z;
    const int tid = threadIdx.x;
    const int tx = tid & 15, ty = tid >> 4;
    const int lc = tid >> 5;
    const int ln = (tid & 31) << 2;

    const float* qp = g_q + (size_t)b * CH * NPIX + (size_t)lc * NPIX + n0 + ln;
    const float* kp = g_k + (size_t)b * CH * NPIX + (size_t)lc * NPIX + m0 + ln;

    float4 qr = *(const float4*)qp;
    float4 kr = *(const float4*)kp;
    *(float4*)&Qs[0][lc][ln] = qr;
    *(float4*)&Ks[0][lc][ln] = kr;
    __syncthreads();

    float acc[8][8];
    #pragma unroll
    for (int i = 0; i < 8; ++i)
        #pragma unroll
        for (int j = 0; j < 8; ++j) acc[i][j] = 0.f;

    const int KT = CH / 8;  // 32
    for (int kt = 0; kt < KT; ++kt) {
        const int cur = kt & 1, nxt = cur ^ 1;
        if (kt + 1 < KT) {
            qr = *(const float4*)(qp + (size_t)(kt + 1) * 8 * NPIX);
            kr = *(const float4*)(kp + (size_t)(kt + 1) * 8 * NPIX);
        }
        #pragma unroll
        for (int kk = 0; kk < 8; ++kk) {
            float a[8], bb[8];
            *(float4*)&a[0]  = *(float4*)&Qs[cur][kk][ty * 8];
            *(float4*)&a[4]  = *(float4*)&Qs[cur][kk][ty * 8 + 4];
            *(float4*)&bb[0] = *(float4*)&Ks[cur][kk][tx * 8];
            *(float4*)&bb[4] = *(float4*)&Ks[cur][kk][tx * 8 + 4];
            #pragma unroll
            for (int i = 0; i < 8; ++i)
                #pragma unroll
                for (int j = 0; j < 8; ++j)
                    acc[i][j] = fmaf(a[i], bb[j], acc[i][j]);
        }
        if (kt + 1 < KT) {
            *(float4*)&Qs[nxt][lc][ln] = qr;
            *(float4*)&Ks[nxt][lc][ln] = kr;
        }
        __syncthreads();
    }

    float* Srow = g_S + (size_t)b * NPIX * NPIX + (size_t)(n0 + ty * 8) * NPIX + m0 + tx * 8;
    #pragma unroll
    for (int i = 0; i < 8; ++i) {
        *(float4*)(Srow + (size_t)i * NPIX)     = *(float4*)&acc[i][0];
        *(float4*)(Srow + (size_t)i * NPIX + 4) = *(float4*)&acc[i][4];
    }
}

// ---------------------------------------------------------------------------
// 3) Row stats: max and 1/sum(exp(x-max)) per row (values kept in registers)
// ---------------------------------------------------------------------------
__global__ __launch_bounds__(256)
void rowstat_kernel()
{
    const int row = blockIdx.x;                     // b*NPIX + n
    const float* S = g_S + (size_t)row * NPIX;
    const int tid = threadIdx.x;

    float4 v[4];
    #pragma unroll
    for (int i = 0; i < 4; ++i)
        v[i] = *(const float4*)(S + i * 1024 + tid * 4);

    float m = v[0].x;
    #pragma unroll
    for (int i = 0; i < 4; ++i) {
        m = fmaxf(m, v[i].x); m = fmaxf(m, v[i].y);
        m = fmaxf(m, v[i].z); m = fmaxf(m, v[i].w);
    }
    m = warpMax(m);

    __shared__ float sm[8], ss[8];
    if ((tid & 31) == 0) sm[tid >> 5] = m;
    __syncthreads();
    float M = sm[0];
    #pragma unroll
    for (int i = 1; i < 8; ++i) M = fmaxf(M, sm[i]);

    float s = 0.f;
    #pragma unroll
    for (int i = 0; i < 4; ++i) {
        s += __expf(v[i].x - M); s += __expf(v[i].y - M);
        s += __expf(v[i].z - M); s += __expf(v[i].w - M);
    }
    s = warpSum(s);
    if ((tid & 31) == 0) ss[tid >> 5] = s;
    __syncthreads();
    if (tid == 0) {
        float tot = 0.f;
        #pragma unroll
        for (int i = 0; i < 8; ++i) tot += ss[i];
        g_mx[row] = M;
        g_rs[row] = 1.f / tot;
    }
}

// ---------------------------------------------------------------------------
// 4) AV: out[b,c,n] = sum_m softmax(S)[b,n,m] * U[b,c,m]
//    Tiles: 128(c) x 128(n), BK=16 over m; exp applied on S-tile load.
// ---------------------------------------------------------------------------
__global__ __launch_bounds__(256, 2)
void av_kernel(const float* __restrict__ U, float* __restrict__ out)
{
    __shared__ float Us[2][16][128];
    __shared__ float Ps[2][16][128];
    const int n0 = blockIdx.x * 128;
    const int c0 = blockIdx.y * 128;
    const int b  = blockIdx.z;
    const int tid = threadIdx.x;
    const int tx = tid & 15, ty = tid >> 4;
    const int r  = tid >> 1;            // row in tile (c for U, n for S)
    const int mb = (tid & 1) << 3;      // 0 or 8

    const float* Up = U   + (size_t)b * CH * NPIX   + (size_t)(c0 + r) * NPIX + mb;
    const float* Sp = g_S + (size_t)b * NPIX * NPIX + (size_t)(n0 + r) * NPIX + mb;
    const float mxv = g_mx[b * NPIX + n0 + r];
    const float rsv = g_rs[b * NPIX + n0 + r];

    float4 u0 = *(const float4*)Up;
    float4 u1 = *(const float4*)(Up + 4);
    float4 s0 = *(const float4*)Sp;
    float4 s1 = *(const float4*)(Sp + 4);

    Us[0][mb + 0][r] = u0.x; Us[0][mb + 1][r] = u0.y;
    Us[0][mb + 2][r] = u0.z; Us[0][mb + 3][r] = u0.w;
    Us[0][mb + 4][r] = u1.x; Us[0][mb + 5][r] = u1.y;
    Us[0][mb + 6][r] = u1.z; Us[0][mb + 7][r] = u1.w;
    Ps[0][mb + 0][r] = __expf(s0.x - mxv) * rsv;
    Ps[0][mb + 1][r] = __expf(s0.y - mxv) * rsv;
    Ps[0][mb + 2][r] = __expf(s0.z - mxv) * rsv;
    Ps[0][mb + 3][r] = __expf(s0.w - mxv) * rsv;
    Ps[0][mb + 4][r] = __expf(s1.x - mxv) * rsv;
    Ps[0][mb + 5][r] = __expf(s1.y - mxv) * rsv;
    Ps[0][mb + 6][r] = __expf(s1.z - mxv) * rsv;
    Ps[0][mb + 7][r] = __expf(s1.w - mxv) * rsv;
    __syncthreads();

    float acc[8][8];
    #pragma unroll
    for (int i = 0; i < 8; ++i)
        #pragma unroll
        for (int j = 0; j < 8; ++j) acc[i][j] = 0.f;

    const int KT = NPIX / 16;  // 256
    for (int kt = 0; kt < KT; ++kt) {
        const int cur = kt & 1, nxt = cur ^ 1;
        if (kt + 1 < KT) {
            u0 = *(const float4*)(Up + (kt + 1) * 16);
            u1 = *(const float4*)(Up + (kt + 1) * 16 + 4);
            s0 = *(const float4*)(Sp + (kt + 1) * 16);
            s1 = *(const float4*)(Sp + (kt + 1) * 16 + 4);
        }
        #pragma unroll
        for (int kk = 0; kk < 16; ++kk) {
            float a[8], bb[8];
            *(float4*)&a[0]  = *(float4*)&Us[cur][kk][ty * 8];
            *(float4*)&a[4]  = *(float4*)&Us[cur][kk][ty * 8 + 4];
            *(float4*)&bb[0] = *(float4*)&Ps[cur][kk][tx * 8];
            *(float4*)&bb[4] = *(float4*)&Ps[cur][kk][tx * 8 + 4];
            #pragma unroll
            for (int i = 0; i < 8; ++i)
                #pragma unroll
                for (int j = 0; j < 8; ++j)
                    acc[i][j] = fmaf(a[i], bb[j], acc[i][j]);
        }
        if (kt + 1 < KT) {
            Us[nxt][mb + 0][r] = u0.x; Us[nxt][mb + 1][r] = u0.y;
            Us[nxt][mb + 2][r] = u0.z; Us[nxt][mb + 3][r] = u0.w;
            Us[nxt][mb + 4][r] = u1.x; Us[nxt][mb + 5][r] = u1.y;
            Us[nxt][mb + 6][r] = u1.z; Us[nxt][mb + 7][r] = u1.w;
            Ps[nxt][mb + 0][r] = __expf(s0.x - mxv) * rsv;
            Ps[nxt][mb + 1][r] = __expf(s0.y - mxv) * rsv;
            Ps[nxt][mb + 2][r] = __expf(s0.z - mxv) * rsv;
            Ps[nxt][mb + 3][r] = __expf(s0.w - mxv) * rsv;
            Ps[nxt][mb + 4][r] = __expf(s1.x - mxv) * rsv;
            Ps[nxt][mb + 5][r] = __expf(s1.y - mxv) * rsv;
            Ps[nxt][mb + 6][r] = __expf(s1.z - mxv) * rsv;
            Ps[nxt][mb + 7][r] = __expf(s1.w - mxv) * rsv;
        }
        __syncthreads();
    }

    float* op = out + (size_t)b * CH * NPIX + (size_t)(c0 + ty * 8) * NPIX + n0 + tx * 8;
    #pragma unroll
    for (int i = 0; i < 8; ++i) {
        *(float4*)(op + (size_t)i * NPIX)     = *(float4*)&acc[i][0];
        *(float4*)(op + (size_t)i * NPIX + 4) = *(float4*)&acc[i][4];
    }
}

// ---------------------------------------------------------------------------
// 5) GroupNorm(+residual) in place on d_out. One block per (b, group).
// ---------------------------------------------------------------------------
__global__ __launch_bounds__(256)
void gn_kernel(float* __restrict__ out, const float* __restrict__ Hand,
               const float* __restrict__ gw, const float* __restrict__ gb)
{
    const int b = blockIdx.x >> 5;
    const int g = blockIdx.x & 31;
    const size_t off = (size_t)b * CH * NPIX + (size_t)g * CPG * NPIX;
    float* base = out + off;
    const float* hb = Hand + off;
    const int tid = threadIdx.x;

    float s1 = 0.f, s2 = 0.f;
    #pragma unroll
    for (int i = 0; i < 32; ++i) {
        float4 v = *(const float4*)(base + i * 1024 + tid * 4);
        s1 += v.x + v.y + v.z + v.w;
        s2 += v.x * v.x + v.y * v.y + v.z * v.z + v.w * v.w;
    }
    s1 = warpSum(s1);
    s2 = warpSum(s2);
    __shared__ float a1[8], a2[8];
    if ((tid & 31) == 0) { a1[tid >> 5] = s1; a2[tid >> 5] = s2; }
    __syncthreads();
    float S1 = 0.f, S2 = 0.f;
    #pragma unroll
    for (int i = 0; i < 8; ++i) { S1 += a1[i]; S2 += a2[i]; }

    const float inv = 1.f / (float)(CPG * NPIX);
    const float mean = S1 * inv;
    const float var  = S2 * inv - mean * mean;
    const float rstd = rsqrtf(var + 1e-5f);

    #pragma unroll
    for (int i = 0; i < 32; ++i) {
        const int f = i * 1024 + tid * 4;
        const int c = g * CPG + (f >> 12);
        const float w  = gw[c];
        const float bi = gb[c];
        float4 v = *(const float4*)(base + f);
        float4 h = *(const float4*)(hb + f);
        v.x = (v.x - mean) * rstd * w + bi + h.x;
        v.y = (v.y - mean) * rstd * w + bi + h.y;
        v.z = (v.z - mean) * rstd * w + bi + h.z;
        v.w = (v.w - mean) * rstd * w + bi + h.w;
        *(float4*)(base + f) = v;
    }
}

// ---------------------------------------------------------------------------
extern "C" void kernel_launch(void* const* d_in, const int* in_sizes, int n_in,
                              void* d_out, int out_size)
{
    const float* Hand = (const float*)d_in[0];
    const float* U    = (const float*)d_in[1];
    const float* WHw  = (const float*)d_in[2];
    const float* WHb  = (const float*)d_in[3];
    const float* WUw  = (const float*)d_in[4];
    const float* WUb  = (const float*)d_in[5];
    const float* gnw  = (const float*)d_in[6];
    const float* gnb  = (const float*)d_in[7];
    float* out = (float*)d_out;

    dim3 pg(NPIX / 128, CH / 128, BATCH);
    proj_kernel<<<pg, 256>>>(WHw, WHb, Hand, 0);   // q from Hand
    proj_kernel<<<pg, 256>>>(WUw, WUb, U,    1);   // k from U

    dim3 sg(NPIX / 128, NPIX / 128, BATCH);
    sgemm_kernel<<<sg, 256>>>();

    rowstat_kernel<<<BATCH * NPIX, 256>>>();

    dim3 ag(NPIX / 128, CH / 128, BATCH);
    av_kernel<<<ag, 256>>>(U, out);

    gn_kernel<<<BATCH * NGRP, 256>>>(out, Hand, gnw, gnb);
}

// round 2
// speedup vs baseline: 2.5344x; 2.5344x over previous
#include <cuda_runtime.h>

#define BATCH 4
#define CH    256
#define NPIX  4096
#define NGRP  32
#define CPG   8

// Scratch (device globals: allocation-free per harness rules)
__device__ float g_q[BATCH * CH * NPIX];
__device__ float g_k[BATCH * CH * NPIX];
__device__ float g_S[(size_t)BATCH * NPIX * NPIX];
__device__ float g_mx[BATCH * NPIX];
__device__ float g_rs[BATCH * NPIX];

// ---------------------------------------------------------------------------
__device__ __forceinline__ float warpMax(float v) {
    #pragma unroll
    for (int o = 16; o > 0; o >>= 1)
        v = fmaxf(v, __shfl_xor_sync(0xffffffffu, v, o));
    return v;
}
__device__ __forceinline__ float warpSum(float v) {
    #pragma unroll
    for (int o = 16; o > 0; o >>= 1)
        v += __shfl_xor_sync(0xffffffffu, v, o);
    return v;
}

// round fp32 -> tf32 bit pattern (kept in a float container)
__device__ __forceinline__ float tf(float x) {
    unsigned r;
    asm("cvt.rna.tf32.f32 %0, %1;" : "=r"(r) : "f"(x));
    return __uint_as_float(r);
}
__device__ __forceinline__ float4 tf4(float4 v) {
    return make_float4(tf(v.x), tf(v.y), tf(v.z), tf(v.w));
}

// D += A*B, m16n8k8 tf32
__device__ __forceinline__ void mma_tf32(float* c, const unsigned* a, const unsigned* b) {
    asm volatile(
        "mma.sync.aligned.m16n8k8.row.col.f32.tf32.tf32.f32 "
        "{%0,%1,%2,%3},{%4,%5,%6,%7},{%8,%9},{%0,%1,%2,%3};"
        : "+f"(c[0]), "+f"(c[1]), "+f"(c[2]), "+f"(c[3])
        : "r"(a[0]), "r"(a[1]), "r"(a[2]), "r"(a[3]), "r"(b[0]), "r"(b[1]));
}

#define PKN 136   // pitch for [k][128] tiles (8k+m bank pattern, conflict-free)
#define PMK 20    // pitch for [128][k16] tiles (20m+k bank pattern, conflict-free)

// ---------------------------------------------------------------------------
// 1) Projection: out[b,o,n] = bias[o] + sum_c W[o,c] * X[b,c,n]
//    A = W [o][c] (row-major M x K) -> Ws[o][c] pitch 20
//    B = X [c][n] (K x N)           -> Xs[c][n] pitch 136
// ---------------------------------------------------------------------------
__global__ __launch_bounds__(256, 2)
void proj_kernel(const float* __restrict__ W, const float* __restrict__ bias,
                 const float* __restrict__ X, int which)
{
    __shared__ float Ws[2][128][PMK];
    __shared__ float Xs[2][16][PKN];
    float* out = which ? g_k : g_q;

    const int n0 = blockIdx.x * 128;
    const int o0 = blockIdx.y * 128;
    const int b  = blockIdx.z;
    const int tid  = threadIdx.x;
    const int lane = tid & 31;
    const int wid  = tid >> 5;
    const int wm   = (wid >> 2) * 64;
    const int wn   = (wid & 3) * 32;

    // W loader: thread -> o row = tid>>1, c base = 8*(tid&1)
    const int wo = tid >> 1;
    const int wc = (tid & 1) * 8;
    const float* Wp = W + (size_t)(o0 + wo) * CH + wc;
    // X loader: row c = tid>>4, col4 = 4*(tid&15) (+64 second half)
    const int xr = tid >> 4;
    const int xc = (tid & 15) * 4;
    const float* Xp = X + (size_t)b * CH * NPIX + (size_t)xr * NPIX + n0 + xc;

    float4 wr0 = *(const float4*)Wp;
    float4 wr1 = *(const float4*)(Wp + 4);
    float4 xr0 = *(const float4*)Xp;
    float4 xr1 = *(const float4*)(Xp + 64);

    *(float4*)&Ws[0][wo][wc]     = tf4(wr0);
    *(float4*)&Ws[0][wo][wc + 4] = tf4(wr1);
    *(float4*)&Xs[0][xr][xc]      = tf4(xr0);
    *(float4*)&Xs[0][xr][xc + 64] = tf4(xr1);
    __syncthreads();

    float acc[4][4][4];
    #pragma unroll
    for (int i = 0; i < 4; ++i)
        #pragma unroll
        for (int j = 0; j < 4; ++j)
            #pragma unroll
            for (int q = 0; q < 4; ++q) acc[i][j][q] = 0.f;

    const int KT = CH / 16;  // 16 stages
    for (int kt = 0; kt < KT; ++kt) {
        const int cur = kt & 1, nxt = cur ^ 1;
        if (kt + 1 < KT) {
            wr0 = *(const float4*)(Wp + (kt + 1) * 16);
            wr1 = *(const float4*)(Wp + (kt + 1) * 16 + 4);
            xr0 = *(const float4*)(Xp + (size_t)(kt + 1) * 16 * NPIX);
            xr1 = *(const float4*)(Xp + (size_t)(kt + 1) * 16 * NPIX + 64);
        }
        #pragma unroll
        for (int ks = 0; ks < 16; ks += 8) {
            unsigned a[4][4], bb[4][2];
            const int fr = lane >> 2, fk = ks + (lane & 3);
            #pragma unroll
            for (int mt = 0; mt < 4; ++mt) {
                const int m = wm + mt * 16 + fr;
                a[mt][0] = __float_as_uint(Ws[cur][m][fk]);
                a[mt][1] = __float_as_uint(Ws[cur][m + 8][fk]);
                a[mt][2] = __float_as_uint(Ws[cur][m][fk + 4]);
                a[mt][3] = __float_as_uint(Ws[cur][m + 8][fk + 4]);
            }
            #pragma unroll
            for (int nt = 0; nt < 4; ++nt) {
                const int n = wn + nt * 8 + fr;
                bb[nt][0] = __float_as_uint(Xs[cur][fk][n]);
                bb[nt][1] = __float_as_uint(Xs[cur][fk + 4][n]);
            }
            #pragma unroll
            for (int mt = 0; mt < 4; ++mt)
                #pragma unroll
                for (int nt = 0; nt < 4; ++nt)
                    mma_tf32(acc[mt][nt], a[mt], bb[nt]);
        }
        if (kt + 1 < KT) {
            *(float4*)&Ws[nxt][wo][wc]     = tf4(wr0);
            *(float4*)&Ws[nxt][wo][wc + 4] = tf4(wr1);
            *(float4*)&Xs[nxt][xr][xc]      = tf4(xr0);
            *(float4*)&Xs[nxt][xr][xc + 64] = tf4(xr1);
        }
        __syncthreads();
    }

    const int fr = lane >> 2, fc = (lane & 3) * 2;
    #pragma unroll
    for (int mt = 0; mt < 4; ++mt) {
        const int row = o0 + wm + mt * 16 + fr;
        const float bv0 = bias[row];
        const float bv1 = bias[row + 8];
        #pragma unroll
        for (int nt = 0; nt < 4; ++nt) {
            const int col = n0 + wn + nt * 8 + fc;
            float* p0 = out + (size_t)b * CH * NPIX + (size_t)row * NPIX + col;
            float* p1 = p0 + (size_t)8 * NPIX;
            *(float2*)p0 = make_float2(acc[mt][nt][0] + bv0, acc[mt][nt][1] + bv0);
            *(float2*)p1 = make_float2(acc[mt][nt][2] + bv1, acc[mt][nt][3] + bv1);
        }
    }
}

// ---------------------------------------------------------------------------
// 2) Logits: S[b,n,m] = sum_c q[b,c,n] * k[b,c,m]
//    A = q^T : Qs[c][n] pitch 136 (direct copy), B = k : Ks[c][m] pitch 136
// ---------------------------------------------------------------------------
__global__ __launch_bounds__(256, 2)
void sgemm_kernel()
{
    __shared__ float Qs[2][16][PKN];
    __shared__ float Ks[2][16][PKN];

    const int m0 = blockIdx.x * 128;
    const int n0 = blockIdx.y * 128;
    const int b  = blockIdx.z;
    const int tid  = threadIdx.x;
    const int lane = tid & 31;
    const int wid  = tid >> 5;
    const int wm   = (wid >> 2) * 64;
    const int wn   = (wid & 3) * 32;

    const int lr = tid >> 4;          // 0..15 (c row)
    const int lc = (tid & 15) * 4;    // col4 base
    const float* qp = g_q + (size_t)b * CH * NPIX + (size_t)lr * NPIX + n0 + lc;
    const float* kp = g_k + (size_t)b * CH * NPIX + (size_t)lr * NPIX + m0 + lc;

    float4 q0 = *(const float4*)qp;
    float4 q1 = *(const float4*)(qp + 64);
    float4 k0 = *(const float4*)kp;
    float4 k1 = *(const float4*)(kp + 64);

    *(float4*)&Qs[0][lr][lc]      = tf4(q0);
    *(float4*)&Qs[0][lr][lc + 64] = tf4(q1);
    *(float4*)&Ks[0][lr][lc]      = tf4(k0);
    *(float4*)&Ks[0][lr][lc + 64] = tf4(k1);
    __syncthreads();

    float acc[4][4][4];
    #pragma unroll
    for (int i = 0; i < 4; ++i)
        #pragma unroll
        for (int j = 0; j < 4; ++j)
            #pragma unroll
            for (int q = 0; q < 4; ++q) acc[i][j][q] = 0.f;

    const int KT = CH / 16;  // 16
    for (int kt = 0; kt < KT; ++kt) {
        const int cur = kt & 1, nxt = cur ^ 1;
        if (kt + 1 < KT) {
            const size_t step = (size_t)(kt + 1) * 16 * NPIX;
            q0 = *(const float4*)(qp + step);
            q1 = *(const float4*)(qp + step + 64);
            k0 = *(const float4*)(kp + step);
            k1 = *(const float4*)(kp + step + 64);
        }
        #pragma unroll
        for (int ks = 0; ks < 16; ks += 8) {
            unsigned a[4][4], bb[4][2];
            const int fr = lane >> 2, fk = ks + (lane & 3);
            #pragma unroll
            for (int mt = 0; mt < 4; ++mt) {
                const int m = wm + mt * 16 + fr;
                a[mt][0] = __float_as_uint(Qs[cur][fk][m]);
                a[mt][1] = __float_as_uint(Qs[cur][fk][m + 8]);
                a[mt][2] = __float_as_uint(Qs[cur][fk + 4][m]);
                a[mt][3] = __float_as_uint(Qs[cur][fk + 4][m + 8]);
            }
            #pragma unroll
            for (int nt = 0; nt < 4; ++nt) {
                const int n = wn + nt * 8 + fr;
                bb[nt][0] = __float_as_uint(Ks[cur][fk][n]);
                bb[nt][1] = __float_as_uint(Ks[cur][fk + 4][n]);
            }
            #pragma unroll
            for (int mt = 0; mt < 4; ++mt)
                #pragma unroll
                for (int nt = 0; nt < 4; ++nt)
                    mma_tf32(acc[mt][nt], a[mt], bb[nt]);
        }
        if (kt + 1 < KT) {
            *(float4*)&Qs[nxt][lr][lc]      = tf4(q0);
            *(float4*)&Qs[nxt][lr][lc + 64] = tf4(q1);
            *(float4*)&Ks[nxt][lr][lc]      = tf4(k0);
            *(float4*)&Ks[nxt][lr][lc + 64] = tf4(k1);
        }
        __syncthreads();
    }

    const int fr = lane >> 2, fc = (lane & 3) * 2;
    float* Sb = g_S + (size_t)b * NPIX * NPIX;
    #pragma unroll
    for (int mt = 0; mt < 4; ++mt) {
        const int row = n0 + wm + mt * 16 + fr;
        #pragma unroll
        for (int nt = 0; nt < 4; ++nt) {
            const int col = m0 + wn + nt * 8 + fc;
            *(float2*)(Sb + (size_t)row * NPIX + col)       = make_float2(acc[mt][nt][0], acc[mt][nt][1]);
            *(float2*)(Sb + (size_t)(row + 8) * NPIX + col) = make_float2(acc[mt][nt][2], acc[mt][nt][3]);
        }
    }
}

// ---------------------------------------------------------------------------
// 3) Row stats: max and 1/sum(exp(x-max)) per row
// ---------------------------------------------------------------------------
__global__ __launch_bounds__(256)
void rowstat_kernel()
{
    const int row = blockIdx.x;
    const float* S = g_S + (size_t)row * NPIX;
    const int tid = threadIdx.x;

    float4 v[4];
    #pragma unroll
    for (int i = 0; i < 4; ++i)
        v[i] = *(const float4*)(S + i * 1024 + tid * 4);

    float m = v[0].x;
    #pragma unroll
    for (int i = 0; i < 4; ++i) {
        m = fmaxf(m, v[i].x); m = fmaxf(m, v[i].y);
        m = fmaxf(m, v[i].z); m = fmaxf(m, v[i].w);
    }
    m = warpMax(m);

    __shared__ float sm[8], ss[8];
    if ((tid & 31) == 0) sm[tid >> 5] = m;
    __syncthreads();
    float M = sm[0];
    #pragma unroll
    for (int i = 1; i < 8; ++i) M = fmaxf(M, sm[i]);

    float s = 0.f;
    #pragma unroll
    for (int i = 0; i < 4; ++i) {
        s += __expf(v[i].x - M); s += __expf(v[i].y - M);
        s += __expf(v[i].z - M); s += __expf(v[i].w - M);
    }
    s = warpSum(s);
    if ((tid & 31) == 0) ss[tid >> 5] = s;
    __syncthreads();
    if (tid == 0) {
        float tot = 0.f;
        #pragma unroll
        for (int i = 0; i < 8; ++i) tot += ss[i];
        g_mx[row] = M;
        g_rs[row] = 1.f / tot;
    }
}

// ---------------------------------------------------------------------------
// 4) AV: out[b,c,n] = sum_m P[b,n,m] * U[b,c,m],  P = softmax(S)
//    A = U [c][m] -> Us[c][k] pitch 20 (natural layout)
//    B = P [n][m] -> Ps[n][k] pitch 20 (natural layout of S rows, exp fused)
// ---------------------------------------------------------------------------
__global__ __launch_bounds__(256, 2)
void av_kernel(const float* __restrict__ U, float* __restrict__ out)
{
    __shared__ float Us[2][128][PMK];
    __shared__ float Ps[2][128][PMK];
    __shared__ float mx_s[128], rs_s[128];

    const int n0 = blockIdx.x * 128;
    const int c0 = blockIdx.y * 128;
    const int b  = blockIdx.z;
    const int tid  = threadIdx.x;
    const int lane = tid & 31;
    const int wid  = tid >> 5;
    const int wm   = (wid >> 2) * 64;
    const int wn   = (wid & 3) * 32;

    if (tid < 128) {
        mx_s[tid] = g_mx[b * NPIX + n0 + tid];
        rs_s[tid] = g_rs[b * NPIX + n0 + tid];
    }

    // loader: rows r = tid>>2 (+64), col4 = 4*(tid&3)
    const int lr = tid >> 2;
    const int lc = (tid & 3) * 4;
    const float* Up = U   + (size_t)b * CH * NPIX   + (size_t)(c0 + lr) * NPIX + lc;
    const float* Sp = g_S + (size_t)b * NPIX * NPIX + (size_t)(n0 + lr) * NPIX + lc;
    const size_t half = (size_t)64 * NPIX;

    float4 u0 = *(const float4*)Up;
    float4 u1 = *(const float4*)(Up + half);
    float4 s0 = *(const float4*)Sp;
    float4 s1 = *(const float4*)(Sp + half);

    {
        // mx_s/rs_s written by threads <128 before this sync? They are read below
        // only AFTER the __syncthreads() that follows the stage-0 stores.
        *(float4*)&Us[0][lr][lc]      = tf4(u0);
        *(float4*)&Us[0][lr + 64][lc] = tf4(u1);
    }
    __syncthreads();   // mx_s/rs_s now visible
    {
        const float m0v = mx_s[lr],      r0v = rs_s[lr];
        const float m1v = mx_s[lr + 64], r1v = rs_s[lr + 64];
        float4 p0 = make_float4(tf(__expf(s0.x - m0v) * r0v), tf(__expf(s0.y - m0v) * r0v),
                                tf(__expf(s0.z - m0v) * r0v), tf(__expf(s0.w - m0v) * r0v));
        float4 p1 = make_float4(tf(__expf(s1.x - m1v) * r1v), tf(__expf(s1.y - m1v) * r1v),
                                tf(__expf(s1.z - m1v) * r1v), tf(__expf(s1.w - m1v) * r1v));
        *(float4*)&Ps[0][lr][lc]      = p0;
        *(float4*)&Ps[0][lr + 64][lc] = p1;
    }
    __syncthreads();

    float acc[4][4][4];
    #pragma unroll
    for (int i = 0; i < 4; ++i)
        #pragma unroll
        for (int j = 0; j < 4; ++j)
            #pragma unroll
            for (int q = 0; q < 4; ++q) acc[i][j][q] = 0.f;

    const float m0v = mx_s[lr],      r0v = rs_s[lr];
    const float m1v = mx_s[lr + 64], r1v = rs_s[lr + 64];

    const int KT = NPIX / 16;  // 256
    for (int kt = 0; kt < KT; ++kt) {
        const int cur = kt & 1, nxt = cur ^ 1;
        if (kt + 1 < KT) {
            u0 = *(const float4*)(Up + (kt + 1) * 16);
            u1 = *(const float4*)(Up + (kt + 1) * 16 + half);
            s0 = *(const float4*)(Sp + (kt + 1) * 16);
            s1 = *(const float4*)(Sp + (kt + 1) * 16 + half);
        }
        #pragma unroll
        for (int ks = 0; ks < 16; ks += 8) {
            unsigned a[4][4], bb[4][2];
            const int fr = lane >> 2, fk = ks + (lane & 3);
            #pragma unroll
            for (int mt = 0; mt < 4; ++mt) {
                const int m = wm + mt * 16 + fr;
                a[mt][0] = __float_as_uint(Us[cur][m][fk]);
                a[mt][1] = __float_as_uint(Us[cur][m + 8][fk]);
                a[mt][2] = __float_as_uint(Us[cur][m][fk + 4]);
                a[mt][3] = __float_as_uint(Us[cur][m + 8][fk + 4]);
            }
            #pragma unroll
            for (int nt = 0; nt < 4; ++nt) {
                const int n = wn + nt * 8 + fr;
                bb[nt][0] = __float_as_uint(Ps[cur][n][fk]);
                bb[nt][1] = __float_as_uint(Ps[cur][n][fk + 4]);
            }
            #pragma unroll
            for (int mt = 0; mt < 4; ++mt)
                #pragma unroll
                for (int nt = 0; nt < 4; ++nt)
                    mma_tf32(acc[mt][nt], a[mt], bb[nt]);
        }
        if (kt + 1 < KT) {
            *(float4*)&Us[nxt][lr][lc]      = tf4(u0);
            *(float4*)&Us[nxt][lr + 64][lc] = tf4(u1);
            float4 p0 = make_float4(tf(__expf(s0.x - m0v) * r0v), tf(__expf(s0.y - m0v) * r0v),
                                    tf(__expf(s0.z - m0v) * r0v), tf(__expf(s0.w - m0v) * r0v));
            float4 p1 = make_float4(tf(__expf(s1.x - m1v) * r1v), tf(__expf(s1.y - m1v) * r1v),
                                    tf(__expf(s1.z - m1v) * r1v), tf(__expf(s1.w - m1v) * r1v));
            *(float4*)&Ps[nxt][lr][lc]      = p0;
            *(float4*)&Ps[nxt][lr + 64][lc] = p1;
        }
        __syncthreads();
    }

    const int fr = lane >> 2, fc = (lane & 3) * 2;
    #pragma unroll
    for (int mt = 0; mt < 4; ++mt) {
        const int row = c0 + wm + mt * 16 + fr;
        #pragma unroll
        for (int nt = 0; nt < 4; ++nt) {
            const int col = n0 + wn + nt * 8 + fc;
            float* p0 = out + (size_t)b * CH * NPIX + (size_t)row * NPIX + col;
            float* p1 = p0 + (size_t)8 * NPIX;
            *(float2*)p0 = make_float2(acc[mt][nt][0], acc[mt][nt][1]);
            *(float2*)p1 = make_float2(acc[mt][nt][2], acc[mt][nt][3]);
        }
    }
}

// ---------------------------------------------------------------------------
// 5) GroupNorm(+residual) in place on d_out. One block per (b, group).
// ---------------------------------------------------------------------------
__global__ __launch_bounds__(256)
void gn_kernel(float* __restrict__ out, const float* __restrict__ Hand,
               const float* __restrict__ gw, const float* __restrict__ gb)
{
    const int b = blockIdx.x >> 5;
    const int g = blockIdx.x & 31;
    const size_t off = (size_t)b * CH * NPIX + (size_t)g * CPG * NPIX;
    float* base = out + off;
    const float* hb = Hand + off;
    const int tid = threadIdx.x;

    float s1 = 0.f, s2 = 0.f;
    #pragma unroll
    for (int i = 0; i < 32; ++i) {
        float4 v = *(const float4*)(base + i * 1024 + tid * 4);
        s1 += v.x + v.y + v.z + v.w;
        s2 += v.x * v.x + v.y * v.y + v.z * v.z + v.w * v.w;
    }
    s1 = warpSum(s1);
    s2 = warpSum(s2);
    __shared__ float a1[8], a2[8];
    if ((tid & 31) == 0) { a1[tid >> 5] = s1; a2[tid >> 5] = s2; }
    __syncthreads();
    float S1 = 0.f, S2 = 0.f;
    #pragma unroll
    for (int i = 0; i < 8; ++i) { S1 += a1[i]; S2 += a2[i]; }

    const float inv = 1.f / (float)(CPG * NPIX);
    const float mean = S1 * inv;
    const float var  = S2 * inv - mean * mean;
    const float rstd = rsqrtf(var + 1e-5f);

    #pragma unroll
    for (int i = 0; i < 32; ++i) {
        const int f = i * 1024 + tid * 4;
        const int c = g * CPG + (f >> 12);
        const float w  = gw[c];
        const float bi = gb[c];
        float4 v = *(const float4*)(base + f);
        float4 h = *(const float4*)(hb + f);
        v.x = (v.x - mean) * rstd * w + bi + h.x;
        v.y = (v.y - mean) * rstd * w + bi + h.y;
        v.z = (v.z - mean) * rstd * w + bi + h.z;
        v.w = (v.w - mean) * rstd * w + bi + h.w;
        *(float4*)(base + f) = v;
    }
}

// ---------------------------------------------------------------------------
extern "C" void kernel_launch(void* const* d_in, const int* in_sizes, int n_in,
                              void* d_out, int out_size)
{
    const float* Hand = (const float*)d_in[0];
    const float* U    = (const float*)d_in[1];
    const float* WHw  = (const float*)d_in[2];
    const float* WHb  = (const float*)d_in[3];
    const float* WUw  = (const float*)d_in[4];
    const float* WUb  = (const float*)d_in[5];
    const float* gnw  = (const float*)d_in[6];
    const float* gnb  = (const float*)d_in[7];
    float* out = (float*)d_out;

    dim3 pg(NPIX / 128, CH / 128, BATCH);
    proj_kernel<<<pg, 256>>>(WHw, WHb, Hand, 0);   // q from Hand
    proj_kernel<<<pg, 256>>>(WUw, WUb, U,    1);   // k from U

    dim3 sg(NPIX / 128, NPIX / 128, BATCH);
    sgemm_kernel<<<sg, 256>>>();

    rowstat_kernel<<<BATCH * NPIX, 256>>>();

    dim3 ag(NPIX / 128, CH / 128, BATCH);
    av_kernel<<<ag, 256>>>(U, out);

    gn_kernel<<<BATCH * NGRP, 256>>>(out, Hand, gnw, gnb);
}

// round 4
// speedup vs baseline: 3.8748x; 1.5289x over previous
#include <cuda_runtime.h>
#include <cuda_fp16.h>
#include <cstdint>

#define BATCH 4
#define CH    256
#define NPIX  4096
#define NGRP  32
#define CPG   8

// ---------------------------------------------------------------------------
// Scratch (device globals)
// ---------------------------------------------------------------------------
__device__ float  g_q [BATCH * CH * NPIX];
__device__ float  g_k [BATCH * CH * NPIX];
__device__ __half g_qt[BATCH * NPIX * CH];           // q^T fp16 [b][n][c]
__device__ __half g_kt[BATCH * NPIX * CH];           // k^T fp16 [b][m][c]
__device__ __half g_ub[BATCH * CH * NPIX];           // U fp16   [b][c][m]
__device__ __half g_P [(size_t)BATCH * NPIX * NPIX]; // exp(s - mx_tile) fp16
__device__ float  g_pmx  [BATCH * NPIX * 32];
__device__ float  g_psum [BATCH * NPIX * 32];
__device__ float  g_scale[BATCH * NPIX * 32];

// ---------------------------------------------------------------------------
// Helpers
// ---------------------------------------------------------------------------
__device__ __forceinline__ float warpMax(float v) {
    #pragma unroll
    for (int o = 16; o > 0; o >>= 1)
        v = fmaxf(v, __shfl_xor_sync(0xffffffffu, v, o));
    return v;
}
__device__ __forceinline__ float warpSum(float v) {
    #pragma unroll
    for (int o = 16; o > 0; o >>= 1)
        v += __shfl_xor_sync(0xffffffffu, v, o);
    return v;
}
__device__ __forceinline__ float tf(float x) {
    unsigned r;
    asm("cvt.rna.tf32.f32 %0, %1;" : "=r"(r) : "f"(x));
    return __uint_as_float(r);
}
__device__ __forceinline__ float4 tf4(float4 v) {
    return make_float4(tf(v.x), tf(v.y), tf(v.z), tf(v.w));
}
__device__ __forceinline__ void mma_tf32(float* c, const unsigned* a, const unsigned* b) {
    asm volatile(
        "mma.sync.aligned.m16n8k8.row.col.f32.tf32.tf32.f32 "
        "{%0,%1,%2,%3},{%4,%5,%6,%7},{%8,%9},{%0,%1,%2,%3};"
        : "+f"(c[0]), "+f"(c[1]), "+f"(c[2]), "+f"(c[3])
        : "r"(a[0]), "r"(a[1]), "r"(a[2]), "r"(a[3]), "r"(b[0]), "r"(b[1]));
}
// fp16 m16n8k16, fp32 accumulate
__device__ __forceinline__ void mma_f16(float* c, const unsigned* a, const unsigned* b) {
    asm volatile(
        "mma.sync.aligned.m16n8k16.row.col.f32.f16.f16.f32 "
        "{%0,%1,%2,%3},{%4,%5,%6,%7},{%8,%9},{%0,%1,%2,%3};"
        : "+f"(c[0]), "+f"(c[1]), "+f"(c[2]), "+f"(c[3])
        : "r"(a[0]), "r"(a[1]), "r"(a[2]), "r"(a[3]), "r"(b[0]), "r"(b[1]));
}

__device__ __forceinline__ uint32_t smem_u32(const void* p) {
    uint32_t a;
    asm("{ .reg .u64 t; cvta.to.shared.u64 t, %1; cvt.u32.u64 %0, t; }" : "=r"(a) : "l"(p));
    return a;
}
__device__ __forceinline__ void cpa16(uint32_t dst, const void* src) {
    asm volatile("cp.async.cg.shared.global [%0], [%1], 16;" :: "r"(dst), "l"(src));
}
#define CPA_COMMIT() asm volatile("cp.async.commit_group;" ::: "memory")
#define CPA_WAIT1()  asm volatile("cp.async.wait_group 1;" ::: "memory")
#define CPA_WAIT0()  asm volatile("cp.async.wait_group 0;" ::: "memory")

// fp16 tile pitch: 40 halfs = 80 B = 20 words -> conflict-free fragment LDS
#define PW        40
#define STG_BYTES (128 * PW * 2)   // 10240 B per 128-row stage

// ---------------------------------------------------------------------------
// 1) Projection (tf32 legacy MMA, proven in R2): out[b,o,n] = bias + W·X
// ---------------------------------------------------------------------------
#define PKN 136
#define PMK 20

__global__ __launch_bounds__(256, 2)
void proj_kernel(const float* __restrict__ W, const float* __restrict__ bias,
                 const float* __restrict__ X, int which)
{
    __shared__ float Ws[2][128][PMK];
    __shared__ float Xs[2][16][PKN];
    float* out = which ? g_k : g_q;

    const int n0 = blockIdx.x * 128;
    const int o0 = blockIdx.y * 128;
    const int b  = blockIdx.z;
    const int tid  = threadIdx.x;
    const int lane = tid & 31;
    const int wid  = tid >> 5;
    const int wm   = (wid >> 2) * 64;
    const int wn   = (wid & 3) * 32;

    const int wo = tid >> 1;
    const int wc = (tid & 1) * 8;
    const float* Wp = W + (size_t)(o0 + wo) * CH + wc;
    const int xr = tid >> 4;
    const int xc = (tid & 15) * 4;
    const float* Xp = X + (size_t)b * CH * NPIX + (size_t)xr * NPIX + n0 + xc;

    float4 wr0 = *(const float4*)Wp;
    float4 wr1 = *(const float4*)(Wp + 4);
    float4 xr0 = *(const float4*)Xp;
    float4 xr1 = *(const float4*)(Xp + 64);

    *(float4*)&Ws[0][wo][wc]     = tf4(wr0);
    *(float4*)&Ws[0][wo][wc + 4] = tf4(wr1);
    *(float4*)&Xs[0][xr][xc]      = tf4(xr0);
    *(float4*)&Xs[0][xr][xc + 64] = tf4(xr1);
    __syncthreads();

    float acc[4][4][4];
    #pragma unroll
    for (int i = 0; i < 4; ++i)
        #pragma unroll
        for (int j = 0; j < 4; ++j)
            #pragma unroll
            for (int q = 0; q < 4; ++q) acc[i][j][q] = 0.f;

    const int KT = CH / 16;
    for (int kt = 0; kt < KT; ++kt) {
        const int cur = kt & 1, nxt = cur ^ 1;
        if (kt + 1 < KT) {
            wr0 = *(const float4*)(Wp + (kt + 1) * 16);
            wr1 = *(const float4*)(Wp + (kt + 1) * 16 + 4);
            xr0 = *(const float4*)(Xp + (size_t)(kt + 1) * 16 * NPIX);
            xr1 = *(const float4*)(Xp + (size_t)(kt + 1) * 16 * NPIX + 64);
        }
        #pragma unroll
        for (int ks = 0; ks < 16; ks += 8) {
            unsigned a[4][4], bb[4][2];
            const int fr = lane >> 2, fk = ks + (lane & 3);
            #pragma unroll
            for (int mt = 0; mt < 4; ++mt) {
                const int m = wm + mt * 16 + fr;
                a[mt][0] = __float_as_uint(Ws[cur][m][fk]);
                a[mt][1] = __float_as_uint(Ws[cur][m + 8][fk]);
                a[mt][2] = __float_as_uint(Ws[cur][m][fk + 4]);
                a[mt][3] = __float_as_uint(Ws[cur][m + 8][fk + 4]);
            }
            #pragma unroll
            for (int nt = 0; nt < 4; ++nt) {
                const int n = wn + nt * 8 + fr;
                bb[nt][0] = __float_as_uint(Xs[cur][fk][n]);
                bb[nt][1] = __float_as_uint(Xs[cur][fk + 4][n]);
            }
            #pragma unroll
            for (int mt = 0; mt < 4; ++mt)
                #pragma unroll
                for (int nt = 0; nt < 4; ++nt)
                    mma_tf32(acc[mt][nt], a[mt], bb[nt]);
        }
        if (kt + 1 < KT) {
            *(float4*)&Ws[nxt][wo][wc]     = tf4(wr0);
            *(float4*)&Ws[nxt][wo][wc + 4] = tf4(wr1);
            *(float4*)&Xs[nxt][xr][xc]      = tf4(xr0);
            *(float4*)&Xs[nxt][xr][xc + 64] = tf4(xr1);
        }
        __syncthreads();
    }

    const int fr = lane >> 2, fc = (lane & 3) * 2;
    #pragma unroll
    for (int mt = 0; mt < 4; ++mt) {
        const int row = o0 + wm + mt * 16 + fr;
        const float bv0 = bias[row];
        const float bv1 = bias[row + 8];
        #pragma unroll
        for (int nt = 0; nt < 4; ++nt) {
            const int col = n0 + wn + nt * 8 + fc;
            float* p0 = out + (size_t)b * CH * NPIX + (size_t)row * NPIX + col;
            float* p1 = p0 + (size_t)8 * NPIX;
            *(float2*)p0 = make_float2(acc[mt][nt][0] + bv0, acc[mt][nt][1] + bv0);
            *(float2*)p1 = make_float2(acc[mt][nt][2] + bv1, acc[mt][nt][3] + bv1);
        }
    }
}

// ---------------------------------------------------------------------------
// 2) Transpose + fp16 convert:  g_q[c][n] -> g_qt[n][c]
// ---------------------------------------------------------------------------
__global__ __launch_bounds__(256)
void tconv_kernel(int which)
{
    __shared__ float t[32][33];
    const float* src = which ? g_k : g_q;
    __half* dst = which ? g_kt : g_qt;

    const int n0 = blockIdx.x * 32;
    const int c0 = blockIdx.y * 32;
    const int b  = blockIdx.z;
    const int tx = threadIdx.x & 31;
    const int ty = threadIdx.x >> 5;

    const float* sp = src + (size_t)b * CH * NPIX + (size_t)(c0 + ty) * NPIX + n0 + tx;
    #pragma unroll
    for (int j = 0; j < 4; ++j)
        t[ty + j * 8][tx] = sp[(size_t)j * 8 * NPIX];
    __syncthreads();

    #pragma unroll
    for (int j = 0; j < 4; ++j) {
        size_t o = (size_t)b * NPIX * CH + (size_t)(n0 + ty + j * 8) * CH + c0 + tx;
        dst[o] = __float2half(t[tx][ty + j * 8]);
    }
}

// ---------------------------------------------------------------------------
// 3) U fp32 -> fp16 (layout preserved)
// ---------------------------------------------------------------------------
__global__ __launch_bounds__(256)
void uconv_kernel(const float* __restrict__ U)
{
    size_t i = ((size_t)blockIdx.x * 256 + threadIdx.x) * 4;
    float4 v = *(const float4*)(U + i);
    __half2 h0 = __floats2half2_rn(v.x, v.y);
    __half2 h1 = __floats2half2_rn(v.z, v.w);
    uint2 w;
    w.x = *(unsigned*)&h0;
    w.y = *(unsigned*)&h1;
    *(uint2*)(g_ub + i) = w;
}

// ---------------------------------------------------------------------------
// 4) Logits GEMM fp16 + fused per-tile softmax -> P fp16, per-tile stats
//    S[n][m] = sum_c qt[n][c] * kt[m][c];  tile 128x128, K=256, BK=32
// ---------------------------------------------------------------------------
__global__ __launch_bounds__(256, 2)
void sgemm_f16()
{
    extern __shared__ char sm_[];
    __half* Qs = (__half*)sm_;
    __half* Ks = (__half*)(sm_ + 3 * STG_BYTES);
    float*  red = (float*)(sm_ + 6 * STG_BYTES);   // [128][4]

    const int m0 = blockIdx.x * 128;
    const int n0 = blockIdx.y * 128;
    const int b  = blockIdx.z;
    const int tid  = threadIdx.x;
    const int lane = tid & 31;
    const int wid  = tid >> 5;
    const int wm   = (wid >> 2) * 64;
    const int wn   = (wid & 3) * 32;

    // loaders: row r = tid>>1, half-offset hb = 0 or 16
    const int r  = tid >> 1;
    const int hb = (tid & 1) * 16;
    const __half* qg = g_qt + (size_t)b * NPIX * CH + (size_t)(n0 + r) * CH + hb;
    const __half* kg = g_kt + (size_t)b * NPIX * CH + (size_t)(m0 + r) * CH + hb;
    const uint32_t qs = smem_u32(Qs) + (uint32_t)(r * 80 + hb * 2);
    const uint32_t ks_ = smem_u32(Ks) + (uint32_t)(r * 80 + hb * 2);

    const int KT = CH / 32;  // 8 stages
    #define SG_ISSUE(kt) do {                                   \
        const uint32_t so = (uint32_t)((kt) % 3) * STG_BYTES;   \
        cpa16(qs + so,      qg + (kt) * 32);                    \
        cpa16(qs + so + 16, qg + (kt) * 32 + 8);                \
        cpa16(ks_ + so,      kg + (kt) * 32);                   \
        cpa16(ks_ + so + 16, kg + (kt) * 32 + 8);               \
        CPA_COMMIT();                                           \
    } while (0)

    SG_ISSUE(0);
    SG_ISSUE(1);

    float acc[4][4][4];
    #pragma unroll
    for (int i = 0; i < 4; ++i)
        #pragma unroll
        for (int j = 0; j < 4; ++j)
            #pragma unroll
            for (int q = 0; q < 4; ++q) acc[i][j][q] = 0.f;

    #pragma unroll 1
    for (int kt = 0; kt < KT; ++kt) {
        if (kt + 1 < KT) { CPA_WAIT1(); } else { CPA_WAIT0(); }
        __syncthreads();
        if (kt + 2 < KT) SG_ISSUE(kt + 2);

        const __half* qb = Qs + (kt % 3) * (128 * PW);
        const __half* kb = Ks + (kt % 3) * (128 * PW);
        #pragma unroll
        for (int ks = 0; ks < 2; ++ks) {
            unsigned a[4][4], bb[4][2];
            const int fr = lane >> 2;
            const int k0 = ks * 16 + (lane & 3) * 2;
            #pragma unroll
            for (int mt = 0; mt < 4; ++mt) {
                const __half* ap = qb + (wm + mt * 16 + fr) * PW + k0;
                a[mt][0] = *(const unsigned*)ap;
                a[mt][1] = *(const unsigned*)(ap + 8 * PW);
                a[mt][2] = *(const unsigned*)(ap + 8);
                a[mt][3] = *(const unsigned*)(ap + 8 * PW + 8);
            }
            #pragma unroll
            for (int nt = 0; nt < 4; ++nt) {
                const __half* bp = kb + (wn + nt * 8 + fr) * PW + k0;
                bb[nt][0] = *(const unsigned*)bp;
                bb[nt][1] = *(const unsigned*)(bp + 8);
            }
            #pragma unroll
            for (int mt = 0; mt < 4; ++mt)
                #pragma unroll
                for (int nt = 0; nt < 4; ++nt)
                    mma_f16(acc[mt][nt], a[mt], bb[nt]);
        }
    }
    #undef SG_ISSUE

    // ---- fused tile softmax ----
    // per-thread row partial max over its 8 columns (8 row-slots)
    float rmax[8];
    #pragma unroll
    for (int mt = 0; mt < 4; ++mt)
        #pragma unroll
        for (int h = 0; h < 2; ++h) {
            float v = fmaxf(acc[mt][0][h * 2], acc[mt][0][h * 2 + 1]);
            #pragma unroll
            for (int nt = 1; nt < 4; ++nt)
                v = fmaxf(v, fmaxf(acc[mt][nt][h * 2], acc[mt][nt][h * 2 + 1]));
            rmax[mt * 2 + h] = v;
        }
    #pragma unroll
    for (int s = 0; s < 8; ++s) {
        rmax[s] = fmaxf(rmax[s], __shfl_xor_sync(0xffffffffu, rmax[s], 1));
        rmax[s] = fmaxf(rmax[s], __shfl_xor_sync(0xffffffffu, rmax[s], 2));
    }
    __syncthreads();   // pipeline smem dead; safe to use red
    if ((lane & 3) == 0) {
        #pragma unroll
        for (int s = 0; s < 8; ++s) {
            const int rr = wm + (s >> 1) * 16 + (lane >> 2) + (s & 1) * 8;
            red[rr * 4 + (wid & 3)] = rmax[s];
        }
    }
    __syncthreads();
    float tmax[8];
    #pragma unroll
    for (int s = 0; s < 8; ++s) {
        const int rr = wm + (s >> 1) * 16 + (lane >> 2) + (s & 1) * 8;
        tmax[s] = fmaxf(fmaxf(red[rr * 4], red[rr * 4 + 1]),
                        fmaxf(red[rr * 4 + 2], red[rr * 4 + 3]));
    }
    __syncthreads();   // before red reuse for sums

    float rsum[8] = {0.f, 0.f, 0.f, 0.f, 0.f, 0.f, 0.f, 0.f};
    #pragma unroll
    for (int mt = 0; mt < 4; ++mt)
        #pragma unroll
        for (int h = 0; h < 2; ++h) {
            const int slot = mt * 2 + h;
            const int rr = wm + mt * 16 + (lane >> 2) + h * 8;
            const float tm = tmax[slot];
            __half* pp = g_P + (size_t)b * NPIX * NPIX
                       + (size_t)(n0 + rr) * NPIX + m0 + wn + (lane & 3) * 2;
            #pragma unroll
            for (int nt = 0; nt < 4; ++nt) {
                const float p0 = __expf(acc[mt][nt][h * 2]     - tm);
                const float p1 = __expf(acc[mt][nt][h * 2 + 1] - tm);
                rsum[slot] += p0 + p1;
                *(__half2*)(pp + nt * 8) = __floats2half2_rn(p0, p1);
            }
        }
    #pragma unroll
    for (int s = 0; s < 8; ++s) {
        rsum[s] += __shfl_xor_sync(0xffffffffu, rsum[s], 1);
        rsum[s] += __shfl_xor_sync(0xffffffffu, rsum[s], 2);
    }
    if ((lane & 3) == 0) {
        #pragma unroll
        for (int s = 0; s < 8; ++s) {
            const int rr = wm + (s >> 1) * 16 + (lane >> 2) + (s & 1) * 8;
            red[rr * 4 + (wid & 3)] = rsum[s];
        }
    }
    __syncthreads();
    if ((wid & 3) == 0 && (lane & 3) == 0) {
        #pragma unroll
        for (int s = 0; s < 8; ++s) {
            const int rr = wm + (s >> 1) * 16 + (lane >> 2) + (s & 1) * 8;
            const float tot = red[rr * 4] + red[rr * 4 + 1] + red[rr * 4 + 2] + red[rr * 4 + 3];
            const int gi = (b * NPIX + n0 + rr) * 32 + blockIdx.x;
            g_pmx[gi]  = tmax[s];
            g_psum[gi] = tot;
        }
    }
}

// ---------------------------------------------------------------------------
// 5) Combine per-tile stats -> per-(row, m-tile) rescale factor
// ---------------------------------------------------------------------------
__global__ __launch_bounds__(256)
void combine_kernel()
{
    const int row  = blockIdx.x * 8 + (threadIdx.x >> 5);
    const int lane = threadIdx.x & 31;
    const float mx = g_pmx [row * 32 + lane];
    const float sm = g_psum[row * 32 + lane];
    const float M  = warpMax(mx);
    const float e  = __expf(mx - M);
    const float tot = warpSum(sm * e);
    g_scale[row * 32 + lane] = e / tot;
}

// ---------------------------------------------------------------------------
// 6) AV GEMM fp16: out[c][n] = sum_m U[c][m] * (P[n][m]*scale[n,mtile])
//    tile 128x128, K=4096, BK=32, scale applied on B fragment (HMUL2)
// ---------------------------------------------------------------------------
__global__ __launch_bounds__(256, 2)
void av_f16(float* __restrict__ out)
{
    extern __shared__ char sm_[];
    __half* Us = (__half*)sm_;
    __half* Ps = (__half*)(sm_ + 3 * STG_BYTES);

    const int n0 = blockIdx.x * 128;
    const int c0 = blockIdx.y * 128;
    const int b  = blockIdx.z;
    const int tid  = threadIdx.x;
    const int lane = tid & 31;
    const int wid  = tid >> 5;
    const int wm   = (wid >> 2) * 64;
    const int wn   = (wid & 3) * 32;

    const int r  = tid >> 1;
    const int hb = (tid & 1) * 16;
    const __half* ug = g_ub + (size_t)b * CH * NPIX   + (size_t)(c0 + r) * NPIX + hb;
    const __half* pg = g_P  + (size_t)b * NPIX * NPIX + (size_t)(n0 + r) * NPIX + hb;
    const uint32_t us = smem_u32(Us) + (uint32_t)(r * 80 + hb * 2);
    const uint32_t ps = smem_u32(Ps) + (uint32_t)(r * 80 + hb * 2);

    const float* scb = g_scale + (size_t)(b * NPIX + n0) * 32;

    const int KT = NPIX / 32;  // 128 stages
    #define AV_ISSUE(kt) do {                                   \
        const uint32_t so = (uint32_t)((kt) % 3) * STG_BYTES;   \
        cpa16(us + so,      ug + (kt) * 32);                    \
        cpa16(us + so + 16, ug + (kt) * 32 + 8);                \
        cpa16(ps + so,      pg + (kt) * 32);                    \
        cpa16(ps + so + 16, pg + (kt) * 32 + 8);                \
        CPA_COMMIT();                                           \
    } while (0)

    AV_ISSUE(0);
    AV_ISSUE(1);

    float acc[4][4][4];
    #pragma unroll
    for (int i = 0; i < 4; ++i)
        #pragma unroll
        for (int j = 0; j < 4; ++j)
            #pragma unroll
            for (int q = 0; q < 4; ++q) acc[i][j][q] = 0.f;

    __half2 sc[4];

    #pragma unroll 1
    for (int kt = 0; kt < KT; ++kt) {
        if ((kt & 3) == 0) {
            // refresh per-row scales for this 128-wide m-tile
            #pragma unroll
            for (int nt = 0; nt < 4; ++nt) {
                const int n = wn + nt * 8 + (lane >> 2);
                sc[nt] = __float2half2_rn(scb[n * 32 + (kt >> 2)]);
            }
        }
        if (kt + 1 < KT) { CPA_WAIT1(); } else { CPA_WAIT0(); }
        __syncthreads();
        if (kt + 2 < KT) AV_ISSUE(kt + 2);

        const __half* ub = Us + (kt % 3) * (128 * PW);
        const __half* pb = Ps + (kt % 3) * (128 * PW);
        #pragma unroll
        for (int ks = 0; ks < 2; ++ks) {
            unsigned a[4][4], bb[4][2];
            const int fr = lane >> 2;
            const int k0 = ks * 16 + (lane & 3) * 2;
            #pragma unroll
            for (int mt = 0; mt < 4; ++mt) {
                const __half* ap = ub + (wm + mt * 16 + fr) * PW + k0;
                a[mt][0] = *(const unsigned*)ap;
                a[mt][1] = *(const unsigned*)(ap + 8 * PW);
                a[mt][2] = *(const unsigned*)(ap + 8);
                a[mt][3] = *(const unsigned*)(ap + 8 * PW + 8);
            }
            #pragma unroll
            for (int nt = 0; nt < 4; ++nt) {
                const __half* bp = pb + (wn + nt * 8 + fr) * PW + k0;
                __half2 b0 = __hmul2(*(const __half2*)bp,       sc[nt]);
                __half2 b1 = __hmul2(*(const __half2*)(bp + 8), sc[nt]);
                bb[nt][0] = *(unsigned*)&b0;
                bb[nt][1] = *(unsigned*)&b1;
            }
            #pragma unroll
            for (int mt = 0; mt < 4; ++mt)
                #pragma unroll
                for (int nt = 0; nt < 4; ++nt)
                    mma_f16(acc[mt][nt], a[mt], bb[nt]);
        }
    }
    #undef AV_ISSUE

    const int fr = lane >> 2, fc = (lane & 3) * 2;
    #pragma unroll
    for (int mt = 0; mt < 4; ++mt) {
        const int row = c0 + wm + mt * 16 + fr;
        #pragma unroll
        for (int nt = 0; nt < 4; ++nt) {
            const int col = n0 + wn + nt * 8 + fc;
            float* p0 = out + (size_t)b * CH * NPIX + (size_t)row * NPIX + col;
            float* p1 = p0 + (size_t)8 * NPIX;
            *(float2*)p0 = make_float2(acc[mt][nt][0], acc[mt][nt][1]);
            *(float2*)p1 = make_float2(acc[mt][nt][2], acc[mt][nt][3]);
        }
    }
}

// ---------------------------------------------------------------------------
// 7) GroupNorm(+residual) in place on d_out
// ---------------------------------------------------------------------------
__global__ __launch_bounds__(256)
void gn_kernel(float* __restrict__ out, const float* __restrict__ Hand,
               const float* __restrict__ gw, const float* __restrict__ gb)
{
    const int b = blockIdx.x >> 5;
    const int g = blockIdx.x & 31;
    const size_t off = (size_t)b * CH * NPIX + (size_t)g * CPG * NPIX;
    float* base = out + off;
    const float* hb = Hand + off;
    const int tid = threadIdx.x;

    float s1 = 0.f, s2 = 0.f;
    #pragma unroll
    for (int i = 0; i < 32; ++i) {
        float4 v = *(const float4*)(base + i * 1024 + tid * 4);
        s1 += v.x + v.y + v.z + v.w;
        s2 += v.x * v.x + v.y * v.y + v.z * v.z + v.w * v.w;
    }
    s1 = warpSum(s1);
    s2 = warpSum(s2);
    __shared__ float a1[8], a2[8];
    if ((tid & 31) == 0) { a1[tid >> 5] = s1; a2[tid >> 5] = s2; }
    __syncthreads();
    float S1 = 0.f, S2 = 0.f;
    #pragma unroll
    for (int i = 0; i < 8; ++i) { S1 += a1[i]; S2 += a2[i]; }

    const float inv  = 1.f / (float)(CPG * NPIX);
    const float mean = S1 * inv;
    const float var  = S2 * inv - mean * mean;
    const float rstd = rsqrtf(var + 1e-5f);

    #pragma unroll
    for (int i = 0; i < 32; ++i) {
        const int f = i * 1024 + tid * 4;
        const int c = g * CPG + (f >> 12);
        const float w  = gw[c];
        const float bi = gb[c];
        float4 v = *(const float4*)(base + f);
        float4 h = *(const float4*)(hb + f);
        v.x = (v.x - mean) * rstd * w + bi + h.x;
        v.y = (v.y - mean) * rstd * w + bi + h.y;
        v.z = (v.z - mean) * rstd * w + bi + h.z;
        v.w = (v.w - mean) * rstd * w + bi + h.w;
        *(float4*)(base + f) = v;
    }
}

// ---------------------------------------------------------------------------
extern "C" void kernel_launch(void* const* d_in, const int* in_sizes, int n_in,
                              void* d_out, int out_size)
{
    const float* Hand = (const float*)d_in[0];
    const float* U    = (const float*)d_in[1];
    const float* WHw  = (const float*)d_in[2];
    const float* WHb  = (const float*)d_in[3];
    const float* WUw  = (const float*)d_in[4];
    const float* WUb  = (const float*)d_in[5];
    const float* gnw  = (const float*)d_in[6];
    const float* gnb  = (const float*)d_in[7];
    float* out = (float*)d_out;

    const int sg_smem = 6 * STG_BYTES + 128 * 4 * 4;  // 63488
    const int av_smem = 6 * STG_BYTES;                // 61440
    cudaFuncSetAttribute(sgemm_f16, cudaFuncAttributeMaxDynamicSharedMemorySize, sg_smem);
    cudaFuncSetAttribute(av_f16,    cudaFuncAttributeMaxDynamicSharedMemorySize, av_smem);

    dim3 pg(NPIX / 128, CH / 128, BATCH);
    proj_kernel<<<pg, 256>>>(WHw, WHb, Hand, 0);
    proj_kernel<<<pg, 256>>>(WUw, WUb, U,    1);

    dim3 tg(NPIX / 32, CH / 32, BATCH);
    tconv_kernel<<<tg, 256>>>(0);
    tconv_kernel<<<tg, 256>>>(1);

    uconv_kernel<<<(BATCH * CH * NPIX) / (256 * 4), 256>>>(U);

    dim3 sg(NPIX / 128, NPIX / 128, BATCH);
    sgemm_f16<<<sg, 256, sg_smem>>>();

    combine_kernel<<<(BATCH * NPIX) / 8, 256>>>();

    dim3 ag(NPIX / 128, CH / 128, BATCH);
    av_f16<<<ag, 256, av_smem>>>(out);

    gn_kernel<<<BATCH * NGRP, 256>>>(out, Hand, gnw, gnb);
}

// round 5
// speedup vs baseline: 4.1254x; 1.0647x over previous
#include <cuda_runtime.h>
#include <cuda_fp16.h>
#include <cstdint>

#define BATCH 4
#define CH    256
#define NPIX  4096
#define NGRP  32
#define CPG   8

// ---------------------------------------------------------------------------
// Scratch (device globals)
// ---------------------------------------------------------------------------
__device__ float  g_q [BATCH * CH * NPIX];
__device__ float  g_k [BATCH * CH * NPIX];
__device__ __half g_qt[BATCH * NPIX * CH];           // q^T fp16 [b][n][c]
__device__ __half g_kt[BATCH * NPIX * CH];           // k^T fp16 [b][m][c]
__device__ __half g_ub[BATCH * CH * NPIX];           // U fp16   [b][c][m]
__device__ __half g_P [(size_t)BATCH * NPIX * NPIX]; // exp(s - mx_tile) fp16
__device__ float  g_pmx  [BATCH * NPIX * 32];
__device__ float  g_psum [BATCH * NPIX * 32];
__device__ float  g_scale[BATCH * NPIX * 32];

// ---------------------------------------------------------------------------
// Helpers
// ---------------------------------------------------------------------------
__device__ __forceinline__ float warpMax(float v) {
    #pragma unroll
    for (int o = 16; o > 0; o >>= 1)
        v = fmaxf(v, __shfl_xor_sync(0xffffffffu, v, o));
    return v;
}
__device__ __forceinline__ float warpSum(float v) {
    #pragma unroll
    for (int o = 16; o > 0; o >>= 1)
        v += __shfl_xor_sync(0xffffffffu, v, o);
    return v;
}
__device__ __forceinline__ float tf(float x) {
    unsigned r;
    asm("cvt.rna.tf32.f32 %0, %1;" : "=r"(r) : "f"(x));
    return __uint_as_float(r);
}
__device__ __forceinline__ float4 tf4(float4 v) {
    return make_float4(tf(v.x), tf(v.y), tf(v.z), tf(v.w));
}
__device__ __forceinline__ void mma_tf32(float* c, const unsigned* a, const unsigned* b) {
    asm volatile(
        "mma.sync.aligned.m16n8k8.row.col.f32.tf32.tf32.f32 "
        "{%0,%1,%2,%3},{%4,%5,%6,%7},{%8,%9},{%0,%1,%2,%3};"
        : "+f"(c[0]), "+f"(c[1]), "+f"(c[2]), "+f"(c[3])
        : "r"(a[0]), "r"(a[1]), "r"(a[2]), "r"(a[3]), "r"(b[0]), "r"(b[1]));
}
// fp16 m16n8k16, fp32 accumulate
__device__ __forceinline__ void mma_f16(float* c, const unsigned* a, const unsigned* b) {
    asm volatile(
        "mma.sync.aligned.m16n8k16.row.col.f32.f16.f16.f32 "
        "{%0,%1,%2,%3},{%4,%5,%6,%7},{%8,%9},{%0,%1,%2,%3};"
        : "+f"(c[0]), "+f"(c[1]), "+f"(c[2]), "+f"(c[3])
        : "r"(a[0]), "r"(a[1]), "r"(a[2]), "r"(a[3]), "r"(b[0]), "r"(b[1]));
}
__device__ __forceinline__ void ldsm_x4(unsigned* r, uint32_t addr) {
    asm volatile("ldmatrix.sync.aligned.m8n8.x4.shared.b16 {%0,%1,%2,%3}, [%4];"
                 : "=r"(r[0]), "=r"(r[1]), "=r"(r[2]), "=r"(r[3]) : "r"(addr));
}

__device__ __forceinline__ uint32_t smem_u32(const void* p) {
    uint32_t a;
    asm("{ .reg .u64 t; cvta.to.shared.u64 t, %1; cvt.u32.u64 %0, t; }" : "=r"(a) : "l"(p));
    return a;
}
__device__ __forceinline__ void cpa16(uint32_t dst, const void* src) {
    asm volatile("cp.async.cg.shared.global [%0], [%1], 16;" :: "r"(dst), "l"(src));
}
#define CPA_COMMIT() asm volatile("cp.async.commit_group;" ::: "memory")
#define CPA_WAIT1()  asm volatile("cp.async.wait_group 1;" ::: "memory")
#define CPA_WAIT0()  asm volatile("cp.async.wait_group 0;" ::: "memory")

// fp16 tile pitch: 40 halfs = 80 B -> conflict-free LDSM phases + STS
#define PW        40
#define STG_BYTES (128 * PW * 2)   // 10240 B per 128-row stage

// ---------------------------------------------------------------------------
// 1) Projection (tf32 legacy MMA, proven): out[b,o,n] = bias + W·X
// ---------------------------------------------------------------------------
#define PKN 136
#define PMK 20

__global__ __launch_bounds__(256, 2)
void proj_kernel(const float* __restrict__ W, const float* __restrict__ bias,
                 const float* __restrict__ X, int which)
{
    __shared__ float Ws[2][128][PMK];
    __shared__ float Xs[2][16][PKN];
    float* out = which ? g_k : g_q;

    const int n0 = blockIdx.x * 128;
    const int o0 = blockIdx.y * 128;
    const int b  = blockIdx.z;
    const int tid  = threadIdx.x;
    const int lane = tid & 31;
    const int wid  = tid >> 5;
    const int wm   = (wid >> 2) * 64;
    const int wn   = (wid & 3) * 32;

    const int wo = tid >> 1;
    const int wc = (tid & 1) * 8;
    const float* Wp = W + (size_t)(o0 + wo) * CH + wc;
    const int xr = tid >> 4;
    const int xc = (tid & 15) * 4;
    const float* Xp = X + (size_t)b * CH * NPIX + (size_t)xr * NPIX + n0 + xc;

    float4 wr0 = *(const float4*)Wp;
    float4 wr1 = *(const float4*)(Wp + 4);
    float4 xr0 = *(const float4*)Xp;
    float4 xr1 = *(const float4*)(Xp + 64);

    *(float4*)&Ws[0][wo][wc]     = tf4(wr0);
    *(float4*)&Ws[0][wo][wc + 4] = tf4(wr1);
    *(float4*)&Xs[0][xr][xc]      = tf4(xr0);
    *(float4*)&Xs[0][xr][xc + 64] = tf4(xr1);
    __syncthreads();

    float acc[4][4][4];
    #pragma unroll
    for (int i = 0; i < 4; ++i)
        #pragma unroll
        for (int j = 0; j < 4; ++j)
            #pragma unroll
            for (int q = 0; q < 4; ++q) acc[i][j][q] = 0.f;

    const int KT = CH / 16;
    for (int kt = 0; kt < KT; ++kt) {
        const int cur = kt & 1, nxt = cur ^ 1;
        if (kt + 1 < KT) {
            wr0 = *(const float4*)(Wp + (kt + 1) * 16);
            wr1 = *(const float4*)(Wp + (kt + 1) * 16 + 4);
            xr0 = *(const float4*)(Xp + (size_t)(kt + 1) * 16 * NPIX);
            xr1 = *(const float4*)(Xp + (size_t)(kt + 1) * 16 * NPIX + 64);
        }
        #pragma unroll
        for (int ks = 0; ks < 16; ks += 8) {
            unsigned a[4][4], bb[4][2];
            const int fr = lane >> 2, fk = ks + (lane & 3);
            #pragma unroll
            for (int mt = 0; mt < 4; ++mt) {
                const int m = wm + mt * 16 + fr;
                a[mt][0] = __float_as_uint(Ws[cur][m][fk]);
                a[mt][1] = __float_as_uint(Ws[cur][m + 8][fk]);
                a[mt][2] = __float_as_uint(Ws[cur][m][fk + 4]);
                a[mt][3] = __float_as_uint(Ws[cur][m + 8][fk + 4]);
            }
            #pragma unroll
            for (int nt = 0; nt < 4; ++nt) {
                const int n = wn + nt * 8 + fr;
                bb[nt][0] = __float_as_uint(Xs[cur][fk][n]);
                bb[nt][1] = __float_as_uint(Xs[cur][fk + 4][n]);
            }
            #pragma unroll
            for (int mt = 0; mt < 4; ++mt)
                #pragma unroll
                for (int nt = 0; nt < 4; ++nt)
                    mma_tf32(acc[mt][nt], a[mt], bb[nt]);
        }
        if (kt + 1 < KT) {
            *(float4*)&Ws[nxt][wo][wc]     = tf4(wr0);
            *(float4*)&Ws[nxt][wo][wc + 4] = tf4(wr1);
            *(float4*)&Xs[nxt][xr][xc]      = tf4(xr0);
            *(float4*)&Xs[nxt][xr][xc + 64] = tf4(xr1);
        }
        __syncthreads();
    }

    const int fr = lane >> 2, fc = (lane & 3) * 2;
    #pragma unroll
    for (int mt = 0; mt < 4; ++mt) {
        const int row = o0 + wm + mt * 16 + fr;
        const float bv0 = bias[row];
        const float bv1 = bias[row + 8];
        #pragma unroll
        for (int nt = 0; nt < 4; ++nt) {
            const int col = n0 + wn + nt * 8 + fc;
            float* p0 = out + (size_t)b * CH * NPIX + (size_t)row * NPIX + col;
            float* p1 = p0 + (size_t)8 * NPIX;
            *(float2*)p0 = make_float2(acc[mt][nt][0] + bv0, acc[mt][nt][1] + bv0);
            *(float2*)p1 = make_float2(acc[mt][nt][2] + bv1, acc[mt][nt][3] + bv1);
        }
    }
}

// ---------------------------------------------------------------------------
// 2) Transpose + fp16 convert:  g_q[c][n] -> g_qt[n][c]
// ---------------------------------------------------------------------------
__global__ __launch_bounds__(256)
void tconv_kernel(int which)
{
    __shared__ float t[32][33];
    const float* src = which ? g_k : g_q;
    __half* dst = which ? g_kt : g_qt;

    const int n0 = blockIdx.x * 32;
    const int c0 = blockIdx.y * 32;
    const int b  = blockIdx.z;
    const int tx = threadIdx.x & 31;
    const int ty = threadIdx.x >> 5;

    const float* sp = src + (size_t)b * CH * NPIX + (size_t)(c0 + ty) * NPIX + n0 + tx;
    #pragma unroll
    for (int j = 0; j < 4; ++j)
        t[ty + j * 8][tx] = sp[(size_t)j * 8 * NPIX];
    __syncthreads();

    #pragma unroll
    for (int j = 0; j < 4; ++j) {
        size_t o = (size_t)b * NPIX * CH + (size_t)(n0 + ty + j * 8) * CH + c0 + tx;
        dst[o] = __float2half(t[tx][ty + j * 8]);
    }
}

// ---------------------------------------------------------------------------
// 3) U fp32 -> fp16 (layout preserved)
// ---------------------------------------------------------------------------
__global__ __launch_bounds__(256)
void uconv_kernel(const float* __restrict__ U)
{
    size_t i = ((size_t)blockIdx.x * 256 + threadIdx.x) * 4;
    float4 v = *(const float4*)(U + i);
    __half2 h0 = __floats2half2_rn(v.x, v.y);
    __half2 h1 = __floats2half2_rn(v.z, v.w);
    uint2 w;
    w.x = *(unsigned*)&h0;
    w.y = *(unsigned*)&h1;
    *(uint2*)(g_ub + i) = w;
}

// ---------------------------------------------------------------------------
// 4) Logits GEMM fp16 (LDSM fragments) + fused per-tile softmax
// ---------------------------------------------------------------------------
__global__ __launch_bounds__(256, 2)
void sgemm_f16()
{
    extern __shared__ char sm_[];
    __half* Qs = (__half*)sm_;
    __half* Ks = (__half*)(sm_ + 3 * STG_BYTES);
    float*  red = (float*)(sm_ + 6 * STG_BYTES);   // [128][4]

    const int m0 = blockIdx.x * 128;
    const int n0 = blockIdx.y * 128;
    const int b  = blockIdx.z;
    const int tid  = threadIdx.x;
    const int lane = tid & 31;
    const int wid  = tid >> 5;
    const int wm   = (wid >> 2) * 64;
    const int wn   = (wid & 3) * 32;

    const int r  = tid >> 1;
    const int hb = (tid & 1) * 16;
    const __half* qg = g_qt + (size_t)b * NPIX * CH + (size_t)(n0 + r) * CH + hb;
    const __half* kg = g_kt + (size_t)b * NPIX * CH + (size_t)(m0 + r) * CH + hb;
    const uint32_t qs = smem_u32(Qs) + (uint32_t)(r * 80 + hb * 2);
    const uint32_t ks_ = smem_u32(Ks) + (uint32_t)(r * 80 + hb * 2);

    // LDSM per-lane fragment base addresses (byte offsets within a stage)
    // A: rows (lane&15), k-half (lane>>4)*8
    const uint32_t afrag = smem_u32(Qs)
        + (uint32_t)(((wm + (lane & 15)) * PW + ((lane >> 4) * 8)) * 2);
    // B: rows (lane&16)>>1 + (lane&7), k-half (lane&8)
    const uint32_t bfrag = smem_u32(Ks)
        + (uint32_t)(((wn + ((lane & 16) >> 1) + (lane & 7)) * PW + (lane & 8)) * 2);

    const int KT = CH / 32;  // 8 stages
    #define SG_ISSUE(kt) do {                                   \
        const uint32_t so = (uint32_t)((kt) % 3) * STG_BYTES;   \
        cpa16(qs + so,      qg + (kt) * 32);                    \
        cpa16(qs + so + 16, qg + (kt) * 32 + 8);                \
        cpa16(ks_ + so,      kg + (kt) * 32);                   \
        cpa16(ks_ + so + 16, kg + (kt) * 32 + 8);               \
        CPA_COMMIT();                                           \
    } while (0)

    SG_ISSUE(0);
    SG_ISSUE(1);

    float acc[4][4][4];
    #pragma unroll
    for (int i = 0; i < 4; ++i)
        #pragma unroll
        for (int j = 0; j < 4; ++j)
            #pragma unroll
            for (int q = 0; q < 4; ++q) acc[i][j][q] = 0.f;

    #pragma unroll 1
    for (int kt = 0; kt < KT; ++kt) {
        if (kt + 1 < KT) { CPA_WAIT1(); } else { CPA_WAIT0(); }
        __syncthreads();
        if (kt + 2 < KT) SG_ISSUE(kt + 2);

        const uint32_t so = (uint32_t)(kt % 3) * STG_BYTES;
        #pragma unroll
        for (int ks = 0; ks < 2; ++ks) {
            unsigned a[4][4], bb[4][2];
            const uint32_t ko = so + (uint32_t)ks * 32;
            #pragma unroll
            for (int mt = 0; mt < 4; ++mt)
                ldsm_x4(a[mt], afrag + ko + (uint32_t)mt * (16 * PW * 2));
            ldsm_x4(&bb[0][0], bfrag + ko);
            ldsm_x4(&bb[2][0], bfrag + ko + (uint32_t)(16 * PW * 2));
            #pragma unroll
            for (int mt = 0; mt < 4; ++mt)
                #pragma unroll
                for (int nt = 0; nt < 4; ++nt)
                    mma_f16(acc[mt][nt], a[mt], bb[nt]);
        }
    }
    #undef SG_ISSUE

    // ---- fused tile softmax ----
    float rmax[8];
    #pragma unroll
    for (int mt = 0; mt < 4; ++mt)
        #pragma unroll
        for (int h = 0; h < 2; ++h) {
            float v = fmaxf(acc[mt][0][h * 2], acc[mt][0][h * 2 + 1]);
            #pragma unroll
            for (int nt = 1; nt < 4; ++nt)
                v = fmaxf(v, fmaxf(acc[mt][nt][h * 2], acc[mt][nt][h * 2 + 1]));
            rmax[mt * 2 + h] = v;
        }
    #pragma unroll
    for (int s = 0; s < 8; ++s) {
        rmax[s] = fmaxf(rmax[s], __shfl_xor_sync(0xffffffffu, rmax[s], 1));
        rmax[s] = fmaxf(rmax[s], __shfl_xor_sync(0xffffffffu, rmax[s], 2));
    }
    __syncthreads();
    if ((lane & 3) == 0) {
        #pragma unroll
        for (int s = 0; s < 8; ++s) {
            const int rr = wm + (s >> 1) * 16 + (lane >> 2) + (s & 1) * 8;
            red[rr * 4 + (wid & 3)] = rmax[s];
        }
    }
    __syncthreads();
    float tmax[8];
    #pragma unroll
    for (int s = 0; s < 8; ++s) {
        const int rr = wm + (s >> 1) * 16 + (lane >> 2) + (s & 1) * 8;
        tmax[s] = fmaxf(fmaxf(red[rr * 4], red[rr * 4 + 1]),
                        fmaxf(red[rr * 4 + 2], red[rr * 4 + 3]));
    }
    __syncthreads();

    float rsum[8] = {0.f, 0.f, 0.f, 0.f, 0.f, 0.f, 0.f, 0.f};
    #pragma unroll
    for (int mt = 0; mt < 4; ++mt)
        #pragma unroll
        for (int h = 0; h < 2; ++h) {
            const int slot = mt * 2 + h;
            const int rr = wm + mt * 16 + (lane >> 2) + h * 8;
            const float tm = tmax[slot];
            __half* pp = g_P + (size_t)b * NPIX * NPIX
                       + (size_t)(n0 + rr) * NPIX + m0 + wn + (lane & 3) * 2;
            #pragma unroll
            for (int nt = 0; nt < 4; ++nt) {
                const float p0 = __expf(acc[mt][nt][h * 2]     - tm);
                const float p1 = __expf(acc[mt][nt][h * 2 + 1] - tm);
                rsum[slot] += p0 + p1;
                *(__half2*)(pp + nt * 8) = __floats2half2_rn(p0, p1);
            }
        }
    #pragma unroll
    for (int s = 0; s < 8; ++s) {
        rsum[s] += __shfl_xor_sync(0xffffffffu, rsum[s], 1);
        rsum[s] += __shfl_xor_sync(0xffffffffu, rsum[s], 2);
    }
    if ((lane & 3) == 0) {
        #pragma unroll
        for (int s = 0; s < 8; ++s) {
            const int rr = wm + (s >> 1) * 16 + (lane >> 2) + (s & 1) * 8;
            red[rr * 4 + (wid & 3)] = rsum[s];
        }
    }
    __syncthreads();
    if ((wid & 3) == 0 && (lane & 3) == 0) {
        #pragma unroll
        for (int s = 0; s < 8; ++s) {
            const int rr = wm + (s >> 1) * 16 + (lane >> 2) + (s & 1) * 8;
            const float tot = red[rr * 4] + red[rr * 4 + 1] + red[rr * 4 + 2] + red[rr * 4 + 3];
            const int gi = (b * NPIX + n0 + rr) * 32 + blockIdx.x;
            g_pmx[gi]  = tmax[s];
            g_psum[gi] = tot;
        }
    }
}

// ---------------------------------------------------------------------------
// 5) Combine per-tile stats -> per-(row, m-tile) rescale factor
// ---------------------------------------------------------------------------
__global__ __launch_bounds__(256)
void combine_kernel()
{
    const int row  = blockIdx.x * 8 + (threadIdx.x >> 5);
    const int lane = threadIdx.x & 31;
    const float mx = g_pmx [row * 32 + lane];
    const float sm = g_psum[row * 32 + lane];
    const float M  = warpMax(mx);
    const float e  = __expf(mx - M);
    const float tot = warpSum(sm * e);
    g_scale[row * 32 + lane] = e / tot;
}

// ---------------------------------------------------------------------------
// 6) AV GEMM fp16 (LDSM fragments): out[c][n] = sum_m U[c][m]*(P[n][m]*scale)
// ---------------------------------------------------------------------------
__global__ __launch_bounds__(256, 2)
void av_f16(float* __restrict__ out)
{
    extern __shared__ char sm_[];
    __half* Us = (__half*)sm_;
    __half* Ps = (__half*)(sm_ + 3 * STG_BYTES);

    const int n0 = blockIdx.x * 128;
    const int c0 = blockIdx.y * 128;
    const int b  = blockIdx.z;
    const int tid  = threadIdx.x;
    const int lane = tid & 31;
    const int wid  = tid >> 5;
    const int wm   = (wid >> 2) * 64;
    const int wn   = (wid & 3) * 32;

    const int r  = tid >> 1;
    const int hb = (tid & 1) * 16;
    const __half* ug = g_ub + (size_t)b * CH * NPIX   + (size_t)(c0 + r) * NPIX + hb;
    const __half* pg = g_P  + (size_t)b * NPIX * NPIX + (size_t)(n0 + r) * NPIX + hb;
    const uint32_t us = smem_u32(Us) + (uint32_t)(r * 80 + hb * 2);
    const uint32_t ps = smem_u32(Ps) + (uint32_t)(r * 80 + hb * 2);

    const uint32_t afrag = smem_u32(Us)
        + (uint32_t)(((wm + (lane & 15)) * PW + ((lane >> 4) * 8)) * 2);
    const uint32_t bfrag = smem_u32(Ps)
        + (uint32_t)(((wn + ((lane & 16) >> 1) + (lane & 7)) * PW + (lane & 8)) * 2);

    const float* scb = g_scale + (size_t)(b * NPIX + n0) * 32;

    const int KT = NPIX / 32;  // 128 stages
    #define AV_ISSUE(kt) do {                                   \
        const uint32_t so = (uint32_t)((kt) % 3) * STG_BYTES;   \
        cpa16(us + so,      ug + (kt) * 32);                    \
        cpa16(us + so + 16, ug + (kt) * 32 + 8);                \
        cpa16(ps + so,      pg + (kt) * 32);                    \
        cpa16(ps + so + 16, pg + (kt) * 32 + 8);                \
        CPA_COMMIT();                                           \
    } while (0)

    AV_ISSUE(0);
    AV_ISSUE(1);

    float acc[4][4][4];
    #pragma unroll
    for (int i = 0; i < 4; ++i)
        #pragma unroll
        for (int j = 0; j < 4; ++j)
            #pragma unroll
            for (int q = 0; q < 4; ++q) acc[i][j][q] = 0.f;

    __half2 sc[4];

    #pragma unroll 1
    for (int kt = 0; kt < KT; ++kt) {
        if ((kt & 3) == 0) {
            #pragma unroll
            for (int nt = 0; nt < 4; ++nt) {
                const int n = wn + nt * 8 + (lane >> 2);
                sc[nt] = __float2half2_rn(scb[n * 32 + (kt >> 2)]);
            }
        }
        if (kt + 1 < KT) { CPA_WAIT1(); } else { CPA_WAIT0(); }
        __syncthreads();
        if (kt + 2 < KT) AV_ISSUE(kt + 2);

        const uint32_t so = (uint32_t)(kt % 3) * STG_BYTES;
        #pragma unroll
        for (int ks = 0; ks < 2; ++ks) {
            unsigned a[4][4], bb[4][2];
            const uint32_t ko = so + (uint32_t)ks * 32;
            #pragma unroll
            for (int mt = 0; mt < 4; ++mt)
                ldsm_x4(a[mt], afrag + ko + (uint32_t)mt * (16 * PW * 2));
            ldsm_x4(&bb[0][0], bfrag + ko);
            ldsm_x4(&bb[2][0], bfrag + ko + (uint32_t)(16 * PW * 2));
            #pragma unroll
            for (int nt = 0; nt < 4; ++nt) {
                __half2 b0 = __hmul2(*(__half2*)&bb[nt][0], sc[nt]);
                __half2 b1 = __hmul2(*(__half2*)&bb[nt][1], sc[nt]);
                bb[nt][0] = *(unsigned*)&b0;
                bb[nt][1] = *(unsigned*)&b1;
            }
            #pragma unroll
            for (int mt = 0; mt < 4; ++mt)
                #pragma unroll
                for (int nt = 0; nt < 4; ++nt)
                    mma_f16(acc[mt][nt], a[mt], bb[nt]);
        }
    }
    #undef AV_ISSUE

    const int fr = lane >> 2, fc = (lane & 3) * 2;
    #pragma unroll
    for (int mt = 0; mt < 4; ++mt) {
        const int row = c0 + wm + mt * 16 + fr;
        #pragma unroll
        for (int nt = 0; nt < 4; ++nt) {
            const int col = n0 + wn + nt * 8 + fc;
            float* p0 = out + (size_t)b * CH * NPIX + (size_t)row * NPIX + col;
            float* p1 = p0 + (size_t)8 * NPIX;
            *(float2*)p0 = make_float2(acc[mt][nt][0], acc[mt][nt][1]);
            *(float2*)p1 = make_float2(acc[mt][nt][2], acc[mt][nt][3]);
        }
    }
}

// ---------------------------------------------------------------------------
// 7) GroupNorm(+residual) in place on d_out — 1024 threads/block
// ---------------------------------------------------------------------------
__global__ __launch_bounds__(1024)
void gn_kernel(float* __restrict__ out, const float* __restrict__ Hand,
               const float* __restrict__ gw, const float* __restrict__ gb)
{
    const int b = blockIdx.x >> 5;
    const int g = blockIdx.x & 31;
    const size_t off = (size_t)b * CH * NPIX + (size_t)g * CPG * NPIX;
    float* base = out + off;
    const float* hb = Hand + off;
    const int tid = threadIdx.x;

    float s1 = 0.f, s2 = 0.f;
    #pragma unroll
    for (int i = 0; i < 8; ++i) {
        float4 v = *(const float4*)(base + i * 4096 + tid * 4);
        s1 += v.x + v.y + v.z + v.w;
        s2 += v.x * v.x + v.y * v.y + v.z * v.z + v.w * v.w;
    }
    s1 = warpSum(s1);
    s2 = warpSum(s2);
    __shared__ float a1[32], a2[32];
    if ((tid & 31) == 0) { a1[tid >> 5] = s1; a2[tid >> 5] = s2; }
    __syncthreads();
    __shared__ float mean_s, rstd_s;
    if (tid < 32) {
        float S1 = a1[tid], S2 = a2[tid];
        S1 = warpSum(S1);
        S2 = warpSum(S2);
        if (tid == 0) {
            const float inv  = 1.f / (float)(CPG * NPIX);
            const float mean = S1 * inv;
            const float var  = S2 * inv - mean * mean;
            mean_s = mean;
            rstd_s = rsqrtf(var + 1e-5f);
        }
    }
    __syncthreads();
    const float mean = mean_s, rstd = rstd_s;

    #pragma unroll
    for (int i = 0; i < 8; ++i) {
        const int f = i * 4096 + tid * 4;
        const int c = g * CPG + (f >> 12);
        const float w  = gw[c];
        const float bi = gb[c];
        float4 v = *(const float4*)(base + f);
        float4 h = *(const float4*)(hb + f);
        v.x = (v.x - mean) * rstd * w + bi + h.x;
        v.y = (v.y - mean) * rstd * w + bi + h.y;
        v.z = (v.z - mean) * rstd * w + bi + h.z;
        v.w = (v.w - mean) * rstd * w + bi + h.w;
        *(float4*)(base + f) = v;
    }
}

// ---------------------------------------------------------------------------
extern "C" void kernel_launch(void* const* d_in, const int* in_sizes, int n_in,
                              void* d_out, int out_size)
{
    const float* Hand = (const float*)d_in[0];
    const float* U    = (const float*)d_in[1];
    const float* WHw  = (const float*)d_in[2];
    const float* WHb  = (const float*)d_in[3];
    const float* WUw  = (const float*)d_in[4];
    const float* WUb  = (const float*)d_in[5];
    const float* gnw  = (const float*)d_in[6];
    const float* gnb  = (const float*)d_in[7];
    float* out = (float*)d_out;

    const int sg_smem = 6 * STG_BYTES + 128 * 4 * 4;  // 63488
    const int av_smem = 6 * STG_BYTES;                // 61440
    cudaFuncSetAttribute(sgemm_f16, cudaFuncAttributeMaxDynamicSharedMemorySize, sg_smem);
    cudaFuncSetAttribute(av_f16,    cudaFuncAttributeMaxDynamicSharedMemorySize, av_smem);

    dim3 pg(NPIX / 128, CH / 128, BATCH);
    proj_kernel<<<pg, 256>>>(WHw, WHb, Hand, 0);
    proj_kernel<<<pg, 256>>>(WUw, WUb, U,    1);

    dim3 tg(NPIX / 32, CH / 32, BATCH);
    tconv_kernel<<<tg, 256>>>(0);
    tconv_kernel<<<tg, 256>>>(1);

    uconv_kernel<<<(BATCH * CH * NPIX) / (256 * 4), 256>>>(U);

    dim3 sg(NPIX / 128, NPIX / 128, BATCH);
    sgemm_f16<<<sg, 256, sg_smem>>>();

    combine_kernel<<<(BATCH * NPIX) / 8, 256>>>();

    dim3 ag(NPIX / 128, CH / 128, BATCH);
    av_f16<<<ag, 256, av_smem>>>(out);

    gn_kernel<<<BATCH * NGRP, 1024>>>(out, Hand, gnw, gnb);
}